// round 17
// baseline (speedup 1.0000x reference)
#include <cuda_runtime.h>
#include <cuda_bf16.h>

// Dilate (zero-insertion upsample) with stride (2,2):
//   in : (16, 64, 256, 256) fp32
//   out: (16, 64, 512, 512) fp32, out[b,c,2i,2j] = in[b,c,i,j], rest 0.
//
// Phase-separation probe (last untested mechanism; targets R/W bus-turnaround
// overhead, the identified residual vs spec BW):
//   Phase 1: cudaMemset2DAsync zeros the odd output rows only
//            (pitch 4KB, width 2KB, height 262144 -> 537MB pure-write burst).
//            Memset nodes are graph-capturable; no allocation.
//   Phase 2: kernel writes even rows only: 268MB read + 537MB write (1:2 mix).
// Total traffic unchanged: 1.342GB floor. Kernel keeps all measured optima:
// one 2KB row per warp, 4 warp-contiguous 512B stores, MLP=4 front-batched
// 256B-coalesced loads, 256 thr/block.

#ifndef DIL_THREADS
#define DIL_THREADS 256
#endif

__global__ void __launch_bounds__(DIL_THREADS)
Dilate_35708358099161_even_rows(const float2* __restrict__ in2,
                                float4* __restrict__ out4)
{
    unsigned int tid  = blockIdx.x * DIL_THREADS + threadIdx.x;
    unsigned int w    = tid >> 5;        // warp id == input row id, 0..262143
    unsigned int lane = tid & 31u;

    unsigned int hin = w & 255u;         // input row within image
    unsigned int bc  = w >> 8;           // image index, 0..1023

    // input float2 base for this lane
    unsigned int base = (bc << 15) + (hin << 7) + lane;

    // four independent 256B-coalesced loads (full 1KB input row per warp)
    float2 a = __ldcs(&in2[base]);
    float2 b = __ldcs(&in2[base + 32]);
    float2 c = __ldcs(&in2[base + 64]);
    float2 d = __ldcs(&in2[base + 96]);

    // even output row base in float4 units: (bc*512 + 2*hin)*128 + lane
    unsigned int v = (bc << 16) + (hin << 8) + lane;

    out4[v]      = make_float4(a.x, 0.f, a.y, 0.f);
    out4[v + 32] = make_float4(b.x, 0.f, b.y, 0.f);
    out4[v + 64] = make_float4(c.x, 0.f, c.y, 0.f);
    out4[v + 96] = make_float4(d.x, 0.f, d.y, 0.f);
}

extern "C" void kernel_launch(void* const* d_in, const int* in_sizes, int n_in,
                              void* d_out, int out_size)
{
    const float2* in2 = (const float2*)d_in[0];
    float4* out4 = (float4*)d_out;
    char* out_bytes = (char*)d_out;

    // Phase 1: zero the odd rows. Out row = 2048B; odd rows start at byte
    // 2048, stride 4096B. height = total_rows/2 = (out_size*4/2048)/2.
    const size_t row_bytes  = 2048;
    const size_t pitch      = 4096;
    const size_t n_odd_rows = ((size_t)out_size * 4 / row_bytes) / 2;  // 262,144
    cudaMemset2DAsync(out_bytes + row_bytes, pitch, 0, row_bytes, n_odd_rows);

    // Phase 2: fill even rows with dilated data. One warp per input row:
    // 262,144 warps -> 8,388,608 threads -> 32,768 blocks.
    const unsigned int nthreads = (unsigned int)(out_size / 32);
    const unsigned int blocks = nthreads / DIL_THREADS;

    Dilate_35708358099161_even_rows<<<blocks, DIL_THREADS>>>(in2, out4);
}